// round 4
// baseline (speedup 1.0000x reference)
#include <cuda_runtime.h>
#include <cuda_bf16.h>

#define VOCAB 100000
#define EMB   300
#define BSZ   2048
#define SEQL  200
#define HID   128
#define OUTD  20

#define EMB4  (EMB / 4)          // 75 float4 per row
#define SPB2  4                  // samples per block in MLP kernel -> grid 512

// rep scratch: [B, EMB] floats (device global — no allocation allowed)
__device__ float4 g_rep4[BSZ * EMB4];

// ---------------------------------------------------------------------------
// Kernel 1: embedding-bag mean.  One thread per (sample, float4 chunk).
// 8-way unrolled token loop -> 8 independent gather loads in flight / thread.
// At the LTS throughput cap (~12.7 TB/s measured) — do not touch.
// ---------------------------------------------------------------------------
__global__ __launch_bounds__(256) void gather_kernel(
    const int*    __restrict__ x,        // [B, L]
    const int*    __restrict__ lengths,  // [B]
    const float4* __restrict__ emb4)     // [VOCAB, 75]
{
    const int gid = blockIdx.x * 256 + threadIdx.x;
    if (gid >= BSZ * EMB4) return;
    const int b = gid / EMB4;
    const int d = gid - b * EMB4;

    const int4* xb4 = (const int4*)(x + (size_t)b * SEQL);  // 200 ints = 50 int4

    float4 a0 = make_float4(0.f, 0.f, 0.f, 0.f);
    float4 a1 = a0, a2 = a0, a3 = a0, a4 = a0, a5 = a0, a6 = a0, a7 = a0;

    // 200 tokens = 25 iterations x 8 tokens
    #pragma unroll 1
    for (int it = 0; it < 25; ++it) {
        const int4 ia = __ldg(xb4 + it * 2 + 0);
        const int4 ib = __ldg(xb4 + it * 2 + 1);
        const float4 v0 = __ldg(emb4 + (size_t)ia.x * EMB4 + d);
        const float4 v1 = __ldg(emb4 + (size_t)ia.y * EMB4 + d);
        const float4 v2 = __ldg(emb4 + (size_t)ia.z * EMB4 + d);
        const float4 v3 = __ldg(emb4 + (size_t)ia.w * EMB4 + d);
        const float4 v4 = __ldg(emb4 + (size_t)ib.x * EMB4 + d);
        const float4 v5 = __ldg(emb4 + (size_t)ib.y * EMB4 + d);
        const float4 v6 = __ldg(emb4 + (size_t)ib.z * EMB4 + d);
        const float4 v7 = __ldg(emb4 + (size_t)ib.w * EMB4 + d);
        a0.x += v0.x; a0.y += v0.y; a0.z += v0.z; a0.w += v0.w;
        a1.x += v1.x; a1.y += v1.y; a1.z += v1.z; a1.w += v1.w;
        a2.x += v2.x; a2.y += v2.y; a2.z += v2.z; a2.w += v2.w;
        a3.x += v3.x; a3.y += v3.y; a3.z += v3.z; a3.w += v3.w;
        a4.x += v4.x; a4.y += v4.y; a4.z += v4.z; a4.w += v4.w;
        a5.x += v5.x; a5.y += v5.y; a5.z += v5.z; a5.w += v5.w;
        a6.x += v6.x; a6.y += v6.y; a6.z += v6.z; a6.w += v6.w;
        a7.x += v7.x; a7.y += v7.y; a7.z += v7.z; a7.w += v7.w;
    }

    const float inv = 1.0f / (float)__ldg(lengths + b);
    float4 r;
    r.x = (a0.x + a1.x + a2.x + a3.x + a4.x + a5.x + a6.x + a7.x) * inv;
    r.y = (a0.y + a1.y + a2.y + a3.y + a4.y + a5.y + a6.y + a7.y) * inv;
    r.z = (a0.z + a1.z + a2.z + a3.z + a4.z + a5.z + a6.z + a7.z) * inv;
    r.w = (a0.w + a1.w + a2.w + a3.w + a4.w + a5.w + a6.w + a7.w) * inv;
    g_rep4[gid] = r;
}

// ---------------------------------------------------------------------------
// Kernel 2: logits = relu(rep @ W1 + b1) @ W2 + b2.
// SPB2=4 samples/block -> grid 512 (≥3.4 CTAs/SM) to fix grid starvation.
// ---------------------------------------------------------------------------
__global__ __launch_bounds__(256) void mlp_kernel(
    const float* __restrict__ W1,   // [EMB, HID]
    const float* __restrict__ b1,   // [HID]
    const float* __restrict__ W2,   // [HID, OUTD]
    const float* __restrict__ b2,   // [OUTD]
    float*       __restrict__ out)  // [B, OUTD]
{
    __shared__ float repT[EMB][SPB2];            // 4.8 KB (transposed rep tile)
    __shared__ float hpart[2][SPB2][HID];        // 4 KB
    __shared__ float hbuf[SPB2][HID];            // 2 KB

    const int tid = threadIdx.x;
    const int b0  = blockIdx.x * SPB2;
    const float* rep = (const float*)g_rep4;     // [B, EMB]

    // load rep tile (coalesced gmem read, transpose into smem)
    for (int i = tid; i < SPB2 * EMB; i += 256) {
        const int s = i / EMB;
        const int d = i - s * EMB;
        repT[d][s] = rep[(size_t)(b0 + s) * EMB + d];
    }
    __syncthreads();

    // GEMM1: h[s][j] = sum_d rep[s][d] * W1[d][j]; d split in halves of 150
    {
        const int j  = tid & (HID - 1);
        const int c  = tid >> 7;                 // d-chunk 0/1
        const int d0 = c * 150;

        float acc[SPB2];
        #pragma unroll
        for (int s = 0; s < SPB2; ++s) acc[s] = 0.0f;

        // 150 = 6 * 25; unroll 6 with independent W1 loads for pipelining
        #pragma unroll 1
        for (int it = 0; it < 25; ++it) {
            const int d = d0 + it * 6;
            float w[6];
            #pragma unroll
            for (int u = 0; u < 6; ++u)
                w[u] = __ldg(&W1[(size_t)(d + u) * HID + j]);
            #pragma unroll
            for (int u = 0; u < 6; ++u) {
                const float4 r0 = *(const float4*)&repT[d + u][0];
                acc[0] += r0.x * w[u]; acc[1] += r0.y * w[u];
                acc[2] += r0.z * w[u]; acc[3] += r0.w * w[u];
            }
        }
        #pragma unroll
        for (int s = 0; s < SPB2; ++s) hpart[c][s][j] = acc[s];
    }
    __syncthreads();

    // combine + bias + relu
    for (int i = tid; i < SPB2 * HID; i += 256) {
        const int s = i >> 7;
        const int j = i & (HID - 1);
        float v = hpart[0][s][j] + hpart[1][s][j] + __ldg(&b1[j]);
        hbuf[s][j] = v > 0.0f ? v : 0.0f;
    }
    __syncthreads();

    // GEMM2: logits[s][o] = sum_k h[s][k] * W2[k][o]
    if (tid < SPB2 * OUTD) {
        const int s = tid / OUTD;
        const int o = tid - s * OUTD;
        float acc = __ldg(&b2[o]);
        #pragma unroll 8
        for (int k = 0; k < HID; ++k)
            acc += hbuf[s][k] * __ldg(&W2[(size_t)k * OUTD + o]);
        out[(size_t)(b0 + s) * OUTD + o] = acc;
    }
}

extern "C" void kernel_launch(void* const* d_in, const int* in_sizes, int n_in,
                              void* d_out, int out_size)
{
    const int*    x       = (const int*)    d_in[0];
    const int*    lengths = (const int*)    d_in[1];
    const float4* emb4    = (const float4*) d_in[2];
    const float*  W1      = (const float*)  d_in[3];
    const float*  b1      = (const float*)  d_in[4];
    const float*  W2      = (const float*)  d_in[5];
    const float*  b2      = (const float*)  d_in[6];
    float*        out     = (float*)        d_out;

    const int gather_items = BSZ * EMB4;                   // 153600
    gather_kernel<<<(gather_items + 255) / 256, 256>>>(x, lengths, emb4);
    mlp_kernel<<<BSZ / SPB2, 256>>>(W1, b1, W2, b2, out);
}

// round 5
// speedup vs baseline: 1.1596x; 1.1596x over previous
#include <cuda_runtime.h>
#include <cuda_bf16.h>

#define VOCAB 100000
#define EMB   300
#define BSZ   2048
#define SEQL  200
#define HID   128
#define OUTD  20

#define EMB4  (EMB / 4)          // 75 float4 per row
#define SPB2  8                  // samples per block in MLP kernel -> grid 256
#define DCHUNKS 8                // d-dimension split in GEMM1

// rep scratch: [B, EMB] floats (device global — no allocation allowed)
__device__ float4 g_rep4[BSZ * EMB4];

// ---------------------------------------------------------------------------
// Kernel 1: embedding-bag mean.  One thread per (sample, float4 chunk).
// 8-way unrolled token loop -> 8 independent gather loads in flight / thread.
// At the LTS throughput cap (~12.7 TB/s measured) — do not touch.
// ---------------------------------------------------------------------------
__global__ __launch_bounds__(256) void gather_kernel(
    const int*    __restrict__ x,        // [B, L]
    const int*    __restrict__ lengths,  // [B]
    const float4* __restrict__ emb4)     // [VOCAB, 75]
{
    const int gid = blockIdx.x * 256 + threadIdx.x;
    if (gid >= BSZ * EMB4) return;
    const int b = gid / EMB4;
    const int d = gid - b * EMB4;

    const int4* xb4 = (const int4*)(x + (size_t)b * SEQL);  // 200 ints = 50 int4

    float4 a0 = make_float4(0.f, 0.f, 0.f, 0.f);
    float4 a1 = a0, a2 = a0, a3 = a0, a4 = a0, a5 = a0, a6 = a0, a7 = a0;

    #pragma unroll 1
    for (int it = 0; it < 25; ++it) {
        const int4 ia = __ldg(xb4 + it * 2 + 0);
        const int4 ib = __ldg(xb4 + it * 2 + 1);
        const float4 v0 = __ldg(emb4 + (size_t)ia.x * EMB4 + d);
        const float4 v1 = __ldg(emb4 + (size_t)ia.y * EMB4 + d);
        const float4 v2 = __ldg(emb4 + (size_t)ia.z * EMB4 + d);
        const float4 v3 = __ldg(emb4 + (size_t)ia.w * EMB4 + d);
        const float4 v4 = __ldg(emb4 + (size_t)ib.x * EMB4 + d);
        const float4 v5 = __ldg(emb4 + (size_t)ib.y * EMB4 + d);
        const float4 v6 = __ldg(emb4 + (size_t)ib.z * EMB4 + d);
        const float4 v7 = __ldg(emb4 + (size_t)ib.w * EMB4 + d);
        a0.x += v0.x; a0.y += v0.y; a0.z += v0.z; a0.w += v0.w;
        a1.x += v1.x; a1.y += v1.y; a1.z += v1.z; a1.w += v1.w;
        a2.x += v2.x; a2.y += v2.y; a2.z += v2.z; a2.w += v2.w;
        a3.x += v3.x; a3.y += v3.y; a3.z += v3.z; a3.w += v3.w;
        a4.x += v4.x; a4.y += v4.y; a4.z += v4.z; a4.w += v4.w;
        a5.x += v5.x; a5.y += v5.y; a5.z += v5.z; a5.w += v5.w;
        a6.x += v6.x; a6.y += v6.y; a6.z += v6.z; a6.w += v6.w;
        a7.x += v7.x; a7.y += v7.y; a7.z += v7.z; a7.w += v7.w;
    }

    const float inv = 1.0f / (float)__ldg(lengths + b);
    float4 r;
    r.x = (a0.x + a1.x + a2.x + a3.x + a4.x + a5.x + a6.x + a7.x) * inv;
    r.y = (a0.y + a1.y + a2.y + a3.y + a4.y + a5.y + a6.y + a7.y) * inv;
    r.z = (a0.z + a1.z + a2.z + a3.z + a4.z + a5.z + a6.z + a7.z) * inv;
    r.w = (a0.w + a1.w + a2.w + a3.w + a4.w + a5.w + a6.w + a7.w) * inv;
    g_rep4[gid] = r;
}

// ---------------------------------------------------------------------------
// Kernel 2: logits = relu(rep @ W1 + b1) @ W2 + b2.
// 8 samples/block, grid 256.  GEMM1: thread (jg, c) owns 4 output columns
// (4*jg..4*jg+3) x 8 samples, d-chunk c (of 8).  W1 loaded via LDG.128,
// FMA:load ratio 32:1, W1 read exactly once per block.
// ---------------------------------------------------------------------------
__global__ __launch_bounds__(256) void mlp_kernel(
    const float* __restrict__ W1,   // [EMB, HID]
    const float* __restrict__ b1,   // [HID]
    const float* __restrict__ W2,   // [HID, OUTD]
    const float* __restrict__ b2,   // [OUTD]
    float*       __restrict__ out)  // [B, OUTD]
{
    __shared__ float repT[EMB][SPB2];              // 9.6 KB
    __shared__ float hpart[DCHUNKS][SPB2][HID];    // 32 KB
    __shared__ float hbuf[SPB2][HID];              // 4 KB

    const int tid = threadIdx.x;
    const int b0  = blockIdx.x * SPB2;
    const float* rep = (const float*)g_rep4;       // [B, EMB]

    // load rep tile (coalesced gmem read, transpose into smem)
    for (int i = tid; i < SPB2 * EMB; i += 256) {
        const int s = i / EMB;
        const int d = i - s * EMB;
        repT[d][s] = rep[(size_t)(b0 + s) * EMB + d];
    }
    __syncthreads();

    // GEMM1
    {
        const int jg = tid & 31;                   // column group: cols 4jg..4jg+3
        const int c  = tid >> 5;                   // d-chunk 0..7
        const int d0 = c * 38;
        const int d1 = (d0 + 38 < EMB) ? (d0 + 38) : EMB;   // last chunk = 34

        float4 acc[SPB2];
        #pragma unroll
        for (int s = 0; s < SPB2; ++s) acc[s] = make_float4(0.f, 0.f, 0.f, 0.f);

        const float4* W14 = (const float4*)W1;     // [EMB][32] float4

        // prefetch first
        float4 w = __ldg(&W14[(size_t)d0 * 32 + jg]);

        #pragma unroll 2
        for (int d = d0; d < d1; ++d) {
            const float4 wc = w;
            if (d + 1 < d1) w = __ldg(&W14[(size_t)(d + 1) * 32 + jg]);  // prefetch next
            const float4 r0 = *(const float4*)&repT[d][0];
            const float4 r1 = *(const float4*)&repT[d][4];
            acc[0].x += r0.x * wc.x; acc[0].y += r0.x * wc.y; acc[0].z += r0.x * wc.z; acc[0].w += r0.x * wc.w;
            acc[1].x += r0.y * wc.x; acc[1].y += r0.y * wc.y; acc[1].z += r0.y * wc.z; acc[1].w += r0.y * wc.w;
            acc[2].x += r0.z * wc.x; acc[2].y += r0.z * wc.y; acc[2].z += r0.z * wc.z; acc[2].w += r0.z * wc.w;
            acc[3].x += r0.w * wc.x; acc[3].y += r0.w * wc.y; acc[3].z += r0.w * wc.z; acc[3].w += r0.w * wc.w;
            acc[4].x += r1.x * wc.x; acc[4].y += r1.x * wc.y; acc[4].z += r1.x * wc.z; acc[4].w += r1.x * wc.w;
            acc[5].x += r1.y * wc.x; acc[5].y += r1.y * wc.y; acc[5].z += r1.y * wc.z; acc[5].w += r1.y * wc.w;
            acc[6].x += r1.z * wc.x; acc[6].y += r1.z * wc.y; acc[6].z += r1.z * wc.z; acc[6].w += r1.z * wc.w;
            acc[7].x += r1.w * wc.x; acc[7].y += r1.w * wc.y; acc[7].z += r1.w * wc.z; acc[7].w += r1.w * wc.w;
        }

        // conflict-free STS.128 per sample
        #pragma unroll
        for (int s = 0; s < SPB2; ++s)
            *(float4*)&hpart[c][s][4 * jg] = acc[s];
    }
    __syncthreads();

    // combine partials + bias + relu
    for (int i = tid; i < SPB2 * HID; i += 256) {
        const int s = i >> 7;
        const int j = i & (HID - 1);
        float v = __ldg(&b1[j]);
        #pragma unroll
        for (int c = 0; c < DCHUNKS; ++c) v += hpart[c][s][j];
        hbuf[s][j] = v > 0.0f ? v : 0.0f;
    }
    __syncthreads();

    // GEMM2: logits[s][o] = sum_k h[s][k] * W2[k][o]
    if (tid < SPB2 * OUTD) {
        const int s = tid / OUTD;
        const int o = tid - s * OUTD;
        float a0 = __ldg(&b2[o]), a1 = 0.f, a2 = 0.f, a3 = 0.f;
        #pragma unroll
        for (int k = 0; k < HID; k += 4) {
            a0 += hbuf[s][k + 0] * __ldg(&W2[(size_t)(k + 0) * OUTD + o]);
            a1 += hbuf[s][k + 1] * __ldg(&W2[(size_t)(k + 1) * OUTD + o]);
            a2 += hbuf[s][k + 2] * __ldg(&W2[(size_t)(k + 2) * OUTD + o]);
            a3 += hbuf[s][k + 3] * __ldg(&W2[(size_t)(k + 3) * OUTD + o]);
        }
        out[(size_t)(b0 + s) * OUTD + o] = (a0 + a1) + (a2 + a3);
    }
}

extern "C" void kernel_launch(void* const* d_in, const int* in_sizes, int n_in,
                              void* d_out, int out_size)
{
    const int*    x       = (const int*)    d_in[0];
    const int*    lengths = (const int*)    d_in[1];
    const float4* emb4    = (const float4*) d_in[2];
    const float*  W1      = (const float*)  d_in[3];
    const float*  b1      = (const float*)  d_in[4];
    const float*  W2      = (const float*)  d_in[5];
    const float*  b2      = (const float*)  d_in[6];
    float*        out     = (float*)        d_out;

    const int gather_items = BSZ * EMB4;                   // 153600
    gather_kernel<<<(gather_items + 255) / 256, 256>>>(x, lengths, emb4);
    mlp_kernel<<<BSZ / SPB2, 256>>>(W1, b1, W2, b2, out);
}